// round 16
// baseline (speedup 1.0000x reference)
#include <cuda_runtime.h>
#include <cuda_bf16.h>
#include <cuda_fp16.h>
#include <cstdint>
#include <stdint.h>
#include <math.h>

#define BB 128
#define TT 32
#define EE 512
#define HH 512
#define VV 10000
#define CF 2048
#define VPAD 10112

#define NCTA_R 128

typedef unsigned long long ull;

// ---------------- scratch (device globals; no allocations allowed) ----------
__device__ float g_h0[BB*HH];
__device__ float g_emb[TT*BB*EE];
__device__ float g_XU[TT*BB*HH];
__device__ float g_XR[TT*BB*HH];
__device__ float g_XC[TT*BB*HH];
__device__ float g_H0a[BB*HH];
__device__ float g_H0b[BB*HH];
__device__ float g_H1[TT*BB*HH];
__device__ float g_u0[BB*HH];
__device__ float g_u1[BB*HH];
__device__ unsigned g_bar;
__device__ unsigned g_gen;
// fragment buffers: tile = 32 lanes x 16B, [kt][pl2][lane32] = 64 uint4/tile
__device__ uint4 g_A2F[TT*16384];        // h1 splits per t (bf16, recurrent use)
__device__ uint4 g_A2H[TT*16384];        // h1 splits per t (fp16, logits use)
__device__ uint4 g_B2F[632*2048];        // out_W frags (fp16; hi plane used)
__device__ uint4 g_embF[256*2048];       // emb frags (bf16)
__device__ uint4 g_H0sFa[16384];
__device__ uint4 g_H0sFb[16384];
__device__ uint4 g_h0sF[16384];
__device__ uint4 g_rhs0F[16384];
__device__ uint4 g_rhs1F[16384];
// weight frags: [gate][nt32][kt][pl2][lane32]
__device__ uint4 g_W0F[3*65536];         // h-part layer0 (K=512)
__device__ uint4 g_WXF[3*65536];         // x-part layer0 (K=512)
__device__ uint4 g_W1F[3*131072];        // layer1 (K=1024)

__device__ __forceinline__ float sigmoidf_(float v){ return 1.f/(1.f+__expf(-v)); }

// packed f32x2 helpers (FFMA2 h0 GEMM)
__device__ __forceinline__ void fma2(ull &acc, ull a, ull b){
    asm("fma.rn.f32x2 %0, %1, %2, %0;" : "+l"(acc) : "l"(a), "l"(b));
}
__device__ __forceinline__ ull dup2(float x){
    ull r; asm("mov.b64 %0, {%1, %1};" : "=l"(r) : "f"(x)); return r;
}
__device__ __forceinline__ float2 unp2(ull v){
    float2 f; asm("mov.b64 {%0, %1}, %2;" : "=f"(f.x), "=f"(f.y) : "l"(v)); return f;
}

// ---------------- mma helpers ------------------------------------------------
__device__ __forceinline__ void mmaU(float* d, const uint4 &a, uint32_t b0, uint32_t b1){
    asm volatile("mma.sync.aligned.m16n8k16.row.col.f32.bf16.bf16.f32 "
        "{%0,%1,%2,%3}, {%4,%5,%6,%7}, {%8,%9}, {%0,%1,%2,%3};"
        : "+f"(d[0]), "+f"(d[1]), "+f"(d[2]), "+f"(d[3])
        : "r"(a.x), "r"(a.y), "r"(a.z), "r"(a.w), "r"(b0), "r"(b1));
}
__device__ __forceinline__ void mmaH(float* d, const uint4 &a, uint32_t b0, uint32_t b1){
    asm volatile("mma.sync.aligned.m16n8k16.row.col.f32.f16.f16.f32 "
        "{%0,%1,%2,%3}, {%4,%5,%6,%7}, {%8,%9}, {%0,%1,%2,%3};"
        : "+f"(d[0]), "+f"(d[1]), "+f"(d[2]), "+f"(d[3])
        : "r"(a.x), "r"(a.y), "r"(a.z), "r"(a.w), "r"(b0), "r"(b1));
}

// split/pack helpers (bf16)
__device__ __forceinline__ uint32_t bfpair(float a, float b){
    __nv_bfloat162 t = __floats2bfloat162_rn(a, b);
    return *reinterpret_cast<uint32_t*>(&t);
}
__device__ __forceinline__ float bfres(float a){
    return a - __bfloat162float(__float2bfloat16(a));
}
__device__ __forceinline__ void store_frag(uint4* dst, const float v[2][4]){
    uint4 HI, LO;
    HI.x = bfpair(v[0][0], v[0][1]); HI.y = bfpair(v[0][2], v[0][3]);
    HI.z = bfpair(v[1][0], v[1][1]); HI.w = bfpair(v[1][2], v[1][3]);
    LO.x = bfpair(bfres(v[0][0]), bfres(v[0][1]));
    LO.y = bfpair(bfres(v[0][2]), bfres(v[0][3]));
    LO.z = bfpair(bfres(v[1][0]), bfres(v[1][1]));
    LO.w = bfpair(bfres(v[1][2]), bfres(v[1][3]));
    __stcg(dst, HI);
    __stcg(dst + 32, LO);
}
// split/pack helpers (fp16)
__device__ __forceinline__ uint32_t hpair(float a, float b){
    __half2 t = __floats2half2_rn(a, b);
    return *reinterpret_cast<uint32_t*>(&t);
}
__device__ __forceinline__ float hres(float a){
    return a - __half2float(__float2half_rn(a));
}
__device__ __forceinline__ void store_fragH(uint4* dst, const float v[2][4]){
    uint4 HI, LO;
    HI.x = hpair(v[0][0], v[0][1]); HI.y = hpair(v[0][2], v[0][3]);
    HI.z = hpair(v[1][0], v[1][1]); HI.w = hpair(v[1][2], v[1][3]);
    LO.x = hpair(hres(v[0][0]), hres(v[0][1]));
    LO.y = hpair(hres(v[0][2]), hres(v[0][3]));
    LO.z = hpair(hres(v[1][0]), hres(v[1][1]));
    LO.w = hpair(hres(v[1][2]), hres(v[1][3]));
    __stcg(dst, HI);
    __stcg(dst + 32, LO);
}

// ---------------- embedding gather ------------------------------------------
__global__ void k_gather(const int* __restrict__ tok, const float* __restrict__ emb){
    int row = blockIdx.x;            // t*BB + b
    int t = row >> 7, b = row & 127;
    int v = tok[b*TT + t];
    const float4* src = (const float4*)(emb + (long)v*EE);
    float4* dst = (float4*)(g_emb + (long)row*EE);
    dst[threadIdx.x] = src[threadIdx.x];
}

// ---------------- h0 GEMM (FFMA2, K=2048, tanh) -----------------------------
__global__ void __launch_bounds__(256)
k_gemmH0(const float* __restrict__ A, const float* __restrict__ Bm,
         const float* __restrict__ bias, float* __restrict__ C)
{
    __shared__ __align__(16) float As[16*132];
    __shared__ __align__(16) float Bs[16*68];
    int tid = threadIdx.x;
    int ty = tid >> 4, tx = tid & 15;
    int n0 = blockIdx.x * 64;
    int ar = tid >> 1, ac = (tid & 1) * 8;
    int br = tid >> 4, bc = (tid & 15) * 4;

    ull acc[4][4] = {};
    float4 a0, a1, b0;

    a0 = *(const float4*)(A + (long)ar*CF + ac);
    a1 = *(const float4*)(A + (long)ar*CF + ac + 4);
    b0 = *(const float4*)(Bm + (long)br*HH + n0 + bc);
    As[(ac+0)*132+ar]=a0.x; As[(ac+1)*132+ar]=a0.y; As[(ac+2)*132+ar]=a0.z; As[(ac+3)*132+ar]=a0.w;
    As[(ac+4)*132+ar]=a1.x; As[(ac+5)*132+ar]=a1.y; As[(ac+6)*132+ar]=a1.z; As[(ac+7)*132+ar]=a1.w;
    *(float4*)&Bs[br*68+bc] = b0;
    __syncthreads();

    int nch = CF >> 4;
    for (int ch = 1; ch <= nch; ch++){
        if (ch < nch){
            int k0 = ch * 16;
            a0 = *(const float4*)(A + (long)ar*CF + k0 + ac);
            a1 = *(const float4*)(A + (long)ar*CF + k0 + ac + 4);
            b0 = *(const float4*)(Bm + (long)(k0+br)*HH + n0 + bc);
        }
#pragma unroll
        for (int kk = 0; kk < 16; kk++){
            ull av[4];
#pragma unroll
            for (int p = 0; p < 4; p++)
                av[p] = *(const ull*)(As + kk*132 + ty*8 + 2*p);
            float4 bv = *(const float4*)(Bs + kk*68 + tx*4);
            ull bb0 = dup2(bv.x), bb1 = dup2(bv.y), bb2 = dup2(bv.z), bb3 = dup2(bv.w);
#pragma unroll
            for (int p = 0; p < 4; p++){
                fma2(acc[p][0], av[p], bb0);
                fma2(acc[p][1], av[p], bb1);
                fma2(acc[p][2], av[p], bb2);
                fma2(acc[p][3], av[p], bb3);
            }
        }
        if (ch < nch){
            __syncthreads();
            As[(ac+0)*132+ar]=a0.x; As[(ac+1)*132+ar]=a0.y; As[(ac+2)*132+ar]=a0.z; As[(ac+3)*132+ar]=a0.w;
            As[(ac+4)*132+ar]=a1.x; As[(ac+5)*132+ar]=a1.y; As[(ac+6)*132+ar]=a1.z; As[(ac+7)*132+ar]=a1.w;
            *(float4*)&Bs[br*68+bc] = b0;
            __syncthreads();
        }
    }

#pragma unroll
    for (int p = 0; p < 4; p++){
#pragma unroll
        for (int j = 0; j < 4; j++){
            float2 v = unp2(acc[p][j]);
            int n = n0 + tx*4 + j;
            float bz = bias[n];
            int row0 = ty*8 + 2*p;
            C[(long)row0*HH + n]     = tanhf(v.x + bz);
            C[(long)(row0+1)*HH + n] = tanhf(v.y + bz);
        }
    }
}

// ---------------- packers ---------------------------------------------------
__global__ void k_packWF(const float* __restrict__ W, uint4* __restrict__ dst, int KT){
    int nt = blockIdx.x, kt = blockIdx.y, l = threadIdx.x;
    int n0 = nt*16 + (l >> 2), k0 = kt*16 + (l & 3)*2;
    float v[2][4];
    v[0][0] = W[(long)(k0  )*HH + n0];   v[0][1] = W[(long)(k0+1)*HH + n0];
    v[0][2] = W[(long)(k0+8)*HH + n0];   v[0][3] = W[(long)(k0+9)*HH + n0];
    v[1][0] = W[(long)(k0  )*HH + n0+8]; v[1][1] = W[(long)(k0+1)*HH + n0+8];
    v[1][2] = W[(long)(k0+8)*HH + n0+8]; v[1][3] = W[(long)(k0+9)*HH + n0+8];
    store_frag(dst + (long)((nt*KT + kt)*2)*32 + l, v);
}

// out_W -> fp16 B-fragments
__global__ void k_packBF(const float* __restrict__ W){
    int nt = blockIdx.x, kt = blockIdx.y, l = threadIdx.x;
    int n0 = nt*16 + (l >> 2), k0 = kt*16 + (l & 3)*2;
    float v[2][4];
#pragma unroll
    for (int h = 0; h < 2; h++){
        int n = n0 + h*8;
        if (n < VV){
            v[h][0] = W[(long)(k0  )*VV + n]; v[h][1] = W[(long)(k0+1)*VV + n];
            v[h][2] = W[(long)(k0+8)*VV + n]; v[h][3] = W[(long)(k0+9)*VV + n];
        } else {
            v[h][0] = v[h][1] = v[h][2] = v[h][3] = 0.f;
        }
    }
    store_fragH(&g_B2F[0] + (nt*32 + kt)*64 + l, v);
}

__global__ void k_packEF(){
    int mt = blockIdx.x, kt = blockIdx.y, l = threadIdx.x;
    int m0 = mt*16 + (l >> 2), k0 = kt*16 + (l & 3)*2;
    float v[2][4];
    v[0][0] = g_emb[(long)(m0  )*EE + k0];   v[0][1] = g_emb[(long)(m0  )*EE + k0+1];
    v[0][2] = g_emb[(long)(m0+8)*EE + k0];   v[0][3] = g_emb[(long)(m0+8)*EE + k0+1];
    v[1][0] = g_emb[(long)(m0  )*EE + k0+8]; v[1][1] = g_emb[(long)(m0  )*EE + k0+9];
    v[1][2] = g_emb[(long)(m0+8)*EE + k0+8]; v[1][3] = g_emb[(long)(m0+8)*EE + k0+9];
    store_frag(&g_embF[0] + (mt*32 + kt)*64 + l, v);
}

__global__ void k_splitH0F(){
    int mt = blockIdx.x, kt = blockIdx.y, l = threadIdx.x;
    int m0 = mt*16 + (l >> 2), k0 = kt*16 + (l & 3)*2;
    float v[2][4];
    v[0][0] = g_h0[(m0  )*HH + k0];   v[0][1] = g_h0[(m0  )*HH + k0+1];
    v[0][2] = g_h0[(m0+8)*HH + k0];   v[0][3] = g_h0[(m0+8)*HH + k0+1];
    v[1][0] = g_h0[(m0  )*HH + k0+8]; v[1][1] = g_h0[(m0  )*HH + k0+9];
    v[1][2] = g_h0[(m0+8)*HH + k0+8]; v[1][3] = g_h0[(m0+8)*HH + k0+9];
    int off = (mt*32 + kt)*64 + l;
    store_frag(&g_H0sFb[0] + off, v);
    store_frag(&g_h0sF[0] + off, v);
}

// ---------------- prep GEMM via fragments: XU/XR/XC = emb@Wx + b ------------
__global__ void __launch_bounds__(256)
k_prepF(const float* __restrict__ bu0, const float* __restrict__ br0,
        const float* __restrict__ bc0)
{
    int lane = threadIdx.x & 31, w = threadIdx.x >> 5;
    int gwp = blockIdx.x * 8 + w;
    int gate = gwp >> 11;
    int rem = gwp & 2047;
    int mg = rem >> 4, ng = rem & 15;

    const float* bias = (gate == 0) ? bu0 : (gate == 1) ? br0 : bc0;
    float* C = (gate == 0) ? g_XU : (gate == 1) ? g_XR : g_XC;

    const uint4* A0 = &g_embF[0] + (long)(mg*2+0)*2048 + lane;
    const uint4* A1 = &g_embF[0] + (long)(mg*2+1)*2048 + lane;
    const uint4* B0 = &g_WXF[0] + (long)gate*65536 + (long)(ng*2+0)*2048 + lane;
    const uint4* B1 = &g_WXF[0] + (long)gate*65536 + (long)(ng*2+1)*2048 + lane;

    float acc[2][2][2][4];
#pragma unroll
    for (int i = 0; i < 2; i++)
#pragma unroll
        for (int j = 0; j < 2; j++)
#pragma unroll
            for (int g = 0; g < 2; g++)
#pragma unroll
                for (int q = 0; q < 4; q++) acc[i][j][g][q] = 0.f;

    uint4 a0h = A0[0], a0l = A0[32], a1h = A1[0], a1l = A1[32];
    uint4 b0h = B0[0], b0l = B0[32], b1h = B1[0], b1l = B1[32];
#pragma unroll 4
    for (int kt = 0; kt < 32; kt++){
        uint4 na0h, na0l, na1h, na1l, nb0h, nb0l, nb1h, nb1l;
        if (kt + 1 < 32){
            int o = (kt+1)*64;
            na0h = A0[o]; na0l = A0[o+32]; na1h = A1[o]; na1l = A1[o+32];
            nb0h = B0[o]; nb0l = B0[o+32]; nb1h = B1[o]; nb1l = B1[o+32];
        } else {
            na0h=a0h; na0l=a0l; na1h=a1h; na1l=a1l;
            nb0h=b0h; nb0l=b0l; nb1h=b1h; nb1l=b1l;
        }
        mmaU(acc[0][0][0], a0h, b0h.x, b0h.y); mmaU(acc[0][0][1], a0h, b0h.z, b0h.w);
        mmaU(acc[0][0][0], a0l, b0h.x, b0h.y); mmaU(acc[0][0][1], a0l, b0h.z, b0h.w);
        mmaU(acc[0][0][0], a0h, b0l.x, b0l.y); mmaU(acc[0][0][1], a0h, b0l.z, b0l.w);

        mmaU(acc[0][1][0], a0h, b1h.x, b1h.y); mmaU(acc[0][1][1], a0h, b1h.z, b1h.w);
        mmaU(acc[0][1][0], a0l, b1h.x, b1h.y); mmaU(acc[0][1][1], a0l, b1h.z, b1h.w);
        mmaU(acc[0][1][0], a0h, b1l.x, b1l.y); mmaU(acc[0][1][1], a0h, b1l.z, b1l.w);

        mmaU(acc[1][0][0], a1h, b0h.x, b0h.y); mmaU(acc[1][0][1], a1h, b0h.z, b0h.w);
        mmaU(acc[1][0][0], a1l, b0h.x, b0h.y); mmaU(acc[1][0][1], a1l, b0h.z, b0h.w);
        mmaU(acc[1][0][0], a1h, b0l.x, b0l.y); mmaU(acc[1][0][1], a1h, b0l.z, b0l.w);

        mmaU(acc[1][1][0], a1h, b1h.x, b1h.y); mmaU(acc[1][1][1], a1h, b1h.z, b1h.w);
        mmaU(acc[1][1][0], a1l, b1h.x, b1h.y); mmaU(acc[1][1][1], a1l, b1h.z, b1h.w);
        mmaU(acc[1][1][0], a1h, b1l.x, b1l.y); mmaU(acc[1][1][1], a1h, b1l.z, b1l.w);

        a0h=na0h; a0l=na0l; a1h=na1h; a1l=na1l;
        b0h=nb0h; b0l=nb0l; b1h=nb1h; b1l=nb1l;
    }

    int lr = lane >> 2, lc2 = (lane & 3) * 2;
#pragma unroll
    for (int i = 0; i < 2; i++){
        int m = mg*32 + i*16 + lr;
        long base = (long)m*HH;
#pragma unroll
        for (int j = 0; j < 2; j++){
#pragma unroll
            for (int g = 0; g < 2; g++){
                int n = ng*32 + j*16 + g*8 + lc2;
                const float* a4 = acc[i][j][g];
                float bz0 = bias[n], bz1 = bias[n+1];
                C[base + n]            = a4[0] + bz0;
                C[base + n + 1]        = a4[1] + bz1;
                C[base + 8*HH + n]     = a4[2] + bz0;
                C[base + 8*HH + n + 1] = a4[3] + bz1;
            }
        }
    }
}

// ---------------- barrier reset + SP-only grid barrier ----------------------
__global__ void k_reset(){ g_bar = 0u; g_gen = 0u; }

__device__ __forceinline__ void gsyncSP(unsigned &my_gen){
    asm volatile("bar.sync 1, 128;" ::: "memory");
    if (threadIdx.x == 0){
        __threadfence();
        my_gen++;
        if (atomicAdd(&g_bar, 1u) == NCTA_R-1u){
            atomicExch(&g_bar, 0u);
            __threadfence();
            atomicExch(&g_gen, my_gen);
        } else {
            while (*(volatile unsigned*)&g_gen < my_gen) { }
            __threadfence();
        }
    }
    asm volatile("bar.sync 1, 128;" ::: "memory");
}

// ---------------- single-stream fragment GEMM (prefetch-1) ------------------
template<int KT>
__device__ __forceinline__ void frag_mm(const uint4* __restrict__ A0,
                                        const uint4* __restrict__ A1,
                                        const uint4* __restrict__ Wb,
                                        float acc[2][4])
{
#pragma unroll
    for (int g = 0; g < 2; g++)
#pragma unroll
        for (int q = 0; q < 4; q++) acc[g][q] = 0.f;

    uint4 cAh = __ldcg(A0), cAl = __ldcg(A0 + 32);
    uint4 cWh = Wb[0], cWl = Wb[32];
#pragma unroll 4
    for (int kt = 0; kt < KT; kt++){
        uint4 nAh, nAl, nWh, nWl;
        if (kt + 1 < KT){
            const uint4* an = ((kt+1) < 32) ? (A0 + (kt+1)*64) : (A1 + (kt+1-32)*64);
            nAh = __ldcg(an); nAl = __ldcg(an + 32);
            nWh = Wb[(kt+1)*64]; nWl = Wb[(kt+1)*64 + 32];
        } else { nAh = cAh; nAl = cAl; nWh = cWh; nWl = cWl; }
        mmaU(acc[0], cAh, cWh.x, cWh.y); mmaU(acc[1], cAh, cWh.z, cWh.w);
        mmaU(acc[0], cAl, cWh.x, cWh.y); mmaU(acc[1], cAl, cWh.z, cWh.w);
        mmaU(acc[0], cAh, cWl.x, cWl.y); mmaU(acc[1], cAh, cWl.z, cWl.w);
        cAh = nAh; cAl = nAl; cWh = nWh; cWl = nWl;
    }
}

// ---------------- logits warp-tile: fp16 2-term, 32x32 for timestep t -------
// A2H read with plain LDG (L1-cached): safe — first touch of these addresses
// happens only after the publish-poll, and L1 is flushed per launch.
__device__ __forceinline__ void logits_tile(int t, int mg, int ng, int lane,
                                            const float* __restrict__ bias,
                                            float* __restrict__ out)
{
    const uint4* A0 = &g_A2H[0] + (long)t*16384 + (mg*2+0)*2048 + lane;
    const uint4* A1 = &g_A2H[0] + (long)t*16384 + (mg*2+1)*2048 + lane;
    const uint4* B0 = &g_B2F[0] + (long)(ng*2+0)*2048 + lane;
    const uint4* B1 = &g_B2F[0] + (long)(ng*2+1)*2048 + lane;

    float acc[2][2][2][4];
#pragma unroll
    for (int i = 0; i < 2; i++)
#pragma unroll
        for (int j = 0; j < 2; j++)
#pragma unroll
            for (int g = 0; g < 2; g++)
#pragma unroll
                for (int q = 0; q < 4; q++) acc[i][j][g][q] = 0.f;

    uint4 a0h = A0[0], a0l = A0[32], a1h = A1[0], a1l = A1[32];
    uint4 b0h = B0[0], b1h = B1[0];
#pragma unroll 4
    for (int kt = 0; kt < 32; kt++){
        uint4 na0h, na0l, na1h, na1l, nb0h, nb1h;
        if (kt + 1 < 32){
            int o = (kt+1)*64;
            na0h = A0[o]; na0l = A0[o+32];
            na1h = A1[o]; na1l = A1[o+32];
            nb0h = B0[o]; nb1h = B1[o];
        } else {
            na0h=a0h; na0l=a0l; na1h=a1h; na1l=a1l;
            nb0h=b0h; nb1h=b1h;
        }
        mmaH(acc[0][0][0], a0h, b0h.x, b0h.y); mmaH(acc[0][0][1], a0h, b0h.z, b0h.w);
        mmaH(acc[0][0][0], a0l, b0h.x, b0h.y); mmaH(acc[0][0][1], a0l, b0h.z, b0h.w);

        mmaH(acc[0][1][0], a0h, b1h.x, b1h.y); mmaH(acc[0][1][1], a0h, b1h.z, b1h.w);
        mmaH(acc[0][1][0], a0l, b1h.x, b1h.y); mmaH(acc[0][1][1], a0l, b1h.z, b1h.w);

        mmaH(acc[1][0][0], a1h, b0h.x, b0h.y); mmaH(acc[1][0][1], a1h, b0h.z, b0h.w);
        mmaH(acc[1][0][0], a1l, b0h.x, b0h.y); mmaH(acc[1][0][1], a1l, b0h.z, b0h.w);

        mmaH(acc[1][1][0], a1h, b1h.x, b1h.y); mmaH(acc[1][1][1], a1h, b1h.z, b1h.w);
        mmaH(acc[1][1][0], a1l, b1h.x, b1h.y); mmaH(acc[1][1][1], a1l, b1h.z, b1h.w);

        a0h=na0h; a0l=na0l; a1h=na1h; a1l=na1l;
        b0h=nb0h; b1h=nb1h;
    }

    int lr = lane >> 2, lc2 = (lane & 3) * 2;
    long sB = TT * (long)VV;
#pragma unroll
    for (int i = 0; i < 2; i++){
        int b = mg*32 + i*16 + lr;
        long base = (long)b*sB + (long)t*VV;
#pragma unroll
        for (int j = 0; j < 2; j++){
#pragma unroll
            for (int g = 0; g < 2; g++){
                int n = (ng*2 + j)*16 + g*8 + lc2;
                const float* a4 = acc[i][j][g];
                if (n < VV){
                    float bz = bias[n];
                    out[base + n]        = a4[0] + bz;
                    out[base + 8*sB + n] = a4[2] + bz;
                }
                if (n + 1 < VV){
                    float bz = bias[n+1];
                    out[base + n + 1]        = a4[1] + bz;
                    out[base + 8*sB + n + 1] = a4[3] + bz;
                }
            }
        }
    }
}

// ---------------- fused persistent kernel: SP warps + free-running logits ---
__global__ void __launch_bounds__(384, 1)
k_recurrentP(const float* __restrict__ bu1, const float* __restrict__ br1,
             const float* __restrict__ bc1,
             const float* __restrict__ outb, float* __restrict__ out)
{
    int tid = threadIdx.x, w = tid >> 5, lane = tid & 31;
    int lr = lane >> 2, lc2 = (lane & 3) * 2;

    if (w >= 4){
        // ---- free-running logits warps: 1024 grid-wide, poll g_gen ----
        int lw = blockIdx.x * 8 + (w - 4);
        for (long idx = lw; idx < (long)TT*1264; idx += 1024){
            int t = (int)(idx / 1264);
            int j = (int)(idx % 1264);
            unsigned need = 2u*t + 4u;
            while (*(volatile unsigned*)&g_gen < need) __nanosleep(200);
            __threadfence();
            logits_tile(t, j & 3, j >> 2, lane, outb, out);
        }
        return;
    }

    // ---- SP warps (0-3): layer-pipelined recurrence ----
    int gw = blockIdx.x * 4 + w;            // 0..511
    unsigned my_gen = 0;

    int gate = gw >> 8;
    int ntA  = (gw >> 3) & 31;
    int mtA  = gw & 7;
    int sel = gw & 1;
    int u2  = gw >> 1;
    int ntB = (u2 >> 3) & 31;
    int mtB = u2 & 7;

    const uint4* WA0 = &g_W0F[0] + (long)gate*65536 + ntA*2048 + lane;
    const uint4* WA1 = &g_W1F[0] + (long)gate*131072 + ntA*4096 + lane;
    const uint4* WB0 = &g_W0F[0] + (long)2*65536   + ntB*2048 + lane;
    const uint4* WB1 = &g_W1F[0] + (long)2*131072  + ntB*4096 + lane;

    uint4* bufF[2] = { &g_H0sFa[0], &g_H0sFb[0] };

    for (int i = 0; i <= TT; i++){
        bool doL0 = (i < TT), doL1 = (i >= 1);
        int t0 = i, t1 = i - 1;
        const uint4* H0rdF = bufF[(t0 + 1) & 1];
        uint4*       H0wrF = bufF[t0 & 1];
        const float* h0prev = (t0 == 0) ? g_h0 : ((t0 & 1) ? g_H0a : g_H0b);
        float*       h0cur  = (t0 & 1) ? g_H0b : g_H0a;
        const float* h1prev = (t1 == 0) ? g_h0 : g_H1 + (long)(t1-1)*BB*HH;
        float*       h1cur  = g_H1 + (long)t1*BB*HH;
        const float* XU = g_XU + (long)t0*BB*HH;
        const float* XR = g_XR + (long)t0*BB*HH;
        const float* XC = g_XC + (long)t0*BB*HH;
        const uint4* h1sF = (t1 == 0) ? &g_h0sF[0] : &g_A2F[0] + (long)(t1-1)*16384;

        // ===== SP1: L0 gates(t0) || L1 gates(t1), shared A first half =====
        {
            float acc0[2][4], acc1[2][4];
#pragma unroll
            for (int g = 0; g < 2; g++)
#pragma unroll
                for (int q = 0; q < 4; q++){ acc0[g][q] = 0.f; acc1[g][q] = 0.f; }

            const uint4* Ab  = H0rdF + mtA*2048 + lane;
            const uint4* A1b = h1sF + mtA*2048 + lane;
            int KTs = doL1 ? 64 : 32;

            uint4 cA0 = __ldcg(Ab), cA1 = __ldcg(Ab + 32);
            uint4 cW00 = WA0[0], cW01 = WA0[32];
            uint4 cW10, cW11;
            if (doL1){ cW10 = WA1[0]; cW11 = WA1[32]; }

#pragma unroll 4
            for (int kt = 0; kt < 64; kt++){
                if (kt >= KTs) break;
                uint4 nA0, nA1, nW00, nW01, nW10, nW11;
                int nk = kt + 1;
                bool hn = nk < KTs;
                if (hn){
                    const uint4* an = (nk < 32) ? (Ab + nk*64) : (A1b + (nk-32)*64);
                    nA0 = __ldcg(an); nA1 = __ldcg(an + 32);
                    if (nk < 32){ nW00 = WA0[nk*64]; nW01 = WA0[nk*64 + 32]; }
                    if (doL1){ nW10 = WA1[nk*64]; nW11 = WA1[nk*64 + 32]; }
                }
                if (doL0 && kt < 32){
                    mmaU(acc0[0], cA0, cW00.x, cW00.y); mmaU(acc0[1], cA0, cW00.z, cW00.w);
                    mmaU(acc0[0], cA1, cW00.x, cW00.y); mmaU(acc0[1], cA1, cW00.z, cW00.w);
                    mmaU(acc0[0], cA0, cW01.x, cW01.y); mmaU(acc0[1], cA0, cW01.z, cW01.w);
                }
                if (doL1){
                    mmaU(acc1[0], cA0, cW10.x, cW10.y); mmaU(acc1[1], cA0, cW10.z, cW10.w);
                    mmaU(acc1[0], cA1, cW10.x, cW10.y); mmaU(acc1[1], cA1, cW10.z, cW10.w);
                    mmaU(acc1[0], cA0, cW11.x, cW11.y); mmaU(acc1[1], cA0, cW11.z, cW11.w);
                }
                if (hn){
                    cA0 = nA0; cA1 = nA1;
                    if (nk < 32){ cW00 = nW00; cW01 = nW01; }
                    if (doL1){ cW10 = nW10; cW11 = nW11; }
                }
            }

            int r0 = mtA*16 + lr;
            if (doL0){
                if (gate == 0){
#pragma unroll
                    for (int g = 0; g < 2; g++){
                        int cg = ntA*16 + g*8 + lc2;
                        int i0 = r0*HH + cg, i1 = (r0+8)*HH + cg;
                        __stcg(&g_u0[i0],   sigmoidf_(acc0[g][0] + XU[i0]));
                        __stcg(&g_u0[i0+1], sigmoidf_(acc0[g][1] + XU[i0+1]));
                        __stcg(&g_u0[i1],   sigmoidf_(acc0[g][2] + XU[i1]));
                        __stcg(&g_u0[i1+1], sigmoidf_(acc0[g][3] + XU[i1+1]));
                    }
                } else {
                    float vv[2][4];
#pragma unroll
                    for (int g = 0; g < 2; g++){
                        int cg = ntA*16 + g*8 + lc2;
                        int i0 = r0*HH + cg, i1 = (r0+8)*HH + cg;
                        vv[g][0] = sigmoidf_(acc0[g][0] + XR[i0])   * __ldcg(&h0prev[i0]);
                        vv[g][1] = sigmoidf_(acc0[g][1] + XR[i0+1]) * __ldcg(&h0prev[i0+1]);
                        vv[g][2] = sigmoidf_(acc0[g][2] + XR[i1])   * __ldcg(&h0prev[i1]);
                        vv[g][3] = sigmoidf_(acc0[g][3] + XR[i1+1]) * __ldcg(&h0prev[i1+1]);
                    }
                    store_frag(&g_rhs0F[0] + mtA*2048 + ntA*64 + lane, vv);
                }
            }
            if (doL1){
                if (gate == 0){
#pragma unroll
                    for (int g = 0; g < 2; g++){
                        int cg = ntA*16 + g*8 + lc2;
                        int i0 = r0*HH + cg, i1 = (r0+8)*HH + cg;
                        __stcg(&g_u1[i0],   sigmoidf_(acc1[g][0] + bu1[cg]));
                        __stcg(&g_u1[i0+1], sigmoidf_(acc1[g][1] + bu1[cg+1]));
                        __stcg(&g_u1[i1],   sigmoidf_(acc1[g][2] + bu1[cg]));
                        __stcg(&g_u1[i1+1], sigmoidf_(acc1[g][3] + bu1[cg+1]));
                    }
                } else {
                    float vv[2][4];
#pragma unroll
                    for (int g = 0; g < 2; g++){
                        int cg = ntA*16 + g*8 + lc2;
                        int i0 = r0*HH + cg, i1 = (r0+8)*HH + cg;
                        vv[g][0] = sigmoidf_(acc1[g][0] + br1[cg])   * __ldcg(&h1prev[i0]);
                        vv[g][1] = sigmoidf_(acc1[g][1] + br1[cg+1]) * __ldcg(&h1prev[i0+1]);
                        vv[g][2] = sigmoidf_(acc1[g][2] + br1[cg])   * __ldcg(&h1prev[i1]);
                        vv[g][3] = sigmoidf_(acc1[g][3] + br1[cg+1]) * __ldcg(&h1prev[i1+1]);
                    }
                    store_frag(&g_rhs1F[0] + mtA*2048 + ntA*64 + lane, vv);
                }
            }
        }
        gsyncSP(my_gen);

        // ===== SP2: L0 c(t0) on even warps || L1 c(t1) on odd warps =====
        if (sel == 0){
            if (doL0){
                float acc[2][4];
                const uint4* A0 = &g_rhs0F[0] + mtB*2048 + lane;
                frag_mm<32>(A0, A0, WB0, acc);
                int r0 = mtB*16 + lr;
                float vv[2][4];
#pragma unroll
                for (int g = 0; g < 2; g++){
                    int cg = ntB*16 + g*8 + lc2;
                    int idx[4] = { r0*HH + cg, r0*HH + cg + 1,
                                   (r0+8)*HH + cg, (r0+8)*HH + cg + 1 };
#pragma unroll
                    for (int j = 0; j < 4; j++){
                        float c0 = tanhf(acc[g][j] + XC[idx[j]]);
                        float uu = __ldcg(&g_u0[idx[j]]);
                        float hp = __ldcg(&h0prev[idx[j]]);
                        float hn = uu*hp + (1.f - uu)*c0;
                        __stcg(&h0cur[idx[j]], hn);
                        vv[g][j] = hn;
                    }
                }
                store_frag(H0wrF + mtB*2048 + ntB*64 + lane, vv);
            }
        } else {
            if (doL1){
                float acc[2][4];
                const uint4* A0 = bufF[t1 & 1] + mtB*2048 + lane;
                const uint4* A1 = &g_rhs1F[0] + mtB*2048 + lane;
                frag_mm<64>(A0, A1, WB1, acc);
                int r0 = mtB*16 + lr;
                float vv[2][4];
#pragma unroll
                for (int g = 0; g < 2; g++){
                    int cg = ntB*16 + g*8 + lc2;
#pragma unroll
                    for (int j = 0; j < 4; j++){
                        int row = r0 + ((j >> 1) ? 8 : 0);
                        int col = cg + (j & 1);
                        int idx = row*HH + col;
                        float c1 = tanhf(acc[g][j] + bc1[col]);
                        float uu = __ldcg(&g_u1[idx]);
                        float hp = __ldcg(&h1prev[idx]);
                        float hn = uu*hp + (1.f - uu)*c1;
                        __stcg(&h1cur[idx], hn);
                        vv[g][j] = hn;
                    }
                }
                store_frag(&g_A2F[0] + (long)t1*16384 + mtB*2048 + ntB*64 + lane, vv);
                store_fragH(&g_A2H[0] + (long)t1*16384 + mtB*2048 + ntB*64 + lane, vv);
            }
        }
        gsyncSP(my_gen);
    }
}

// ---------------- final state copy ------------------------------------------
__global__ void k_copy_final(const float* __restrict__ h0f,
                             const float* __restrict__ h1f,
                             float* __restrict__ out)
{
    int i = blockIdx.x * blockDim.x + threadIdx.x;
    if (i < BB*HH){
        out[i]         = h0f[i];
        out[BB*HH + i] = h1f[i];
    }
}

// ---------------- launch ----------------------------------------------------
extern "C" void kernel_launch(void* const* d_in, const int* in_sizes, int n_in,
                              void* d_out, int out_size)
{
    const float* cnn = (const float*)d_in[0];
    const int*   tok = (const int*)  d_in[1];
    const float* emb = (const float*)d_in[2];
    const float* inW = (const float*)d_in[3];
    const float* inb = (const float*)d_in[4];
    const float* Wu0 = (const float*)d_in[5];
    const float* bu0 = (const float*)d_in[6];
    const float* Wr0 = (const float*)d_in[7];
    const float* br0 = (const float*)d_in[8];
    const float* Wc0 = (const float*)d_in[9];
    const float* bc0 = (const float*)d_in[10];
    const float* Wu1 = (const float*)d_in[11];
    const float* bu1 = (const float*)d_in[12];
    const float* Wr1 = (const float*)d_in[13];
    const float* br1 = (const float*)d_in[14];
    const float* Wc1 = (const float*)d_in[15];
    const float* bc1 = (const float*)d_in[16];
    const float* outW= (const float*)d_in[17];
    const float* outb= (const float*)d_in[18];
    float* out = (float*)d_out;

    float *ph0,*pH0b,*pH1;
    uint4 *pW0F, *pWXF, *pW1F;
    cudaGetSymbolAddress((void**)&ph0,  g_h0);
    cudaGetSymbolAddress((void**)&pH0b, g_H0b);
    cudaGetSymbolAddress((void**)&pH1,  g_H1);
    cudaGetSymbolAddress((void**)&pW0F, g_W0F);
    cudaGetSymbolAddress((void**)&pWXF, g_WXF);
    cudaGetSymbolAddress((void**)&pW1F, g_W1F);

    // h0 = tanh(cnn @ in_W + in_b)
    k_gemmH0<<<8, 256>>>(cnn, inW, inb, ph0);
    // gather embeddings
    k_gather<<<TT*BB, 128>>>(tok, emb);
    // logits-weight fragment pack (fp16)
    k_packBF<<<dim3(632, 32), 32>>>(outW);
    // recurrent-weight fragment packs (h-parts + layer1)
    const float* Wu0h = Wu0 + (long)EE*HH;
    const float* Wr0h = Wr0 + (long)EE*HH;
    const float* Wc0h = Wc0 + (long)EE*HH;
    k_packWF<<<dim3(32, 32), 32>>>(Wu0h, pW0F + (long)0*65536, 32);
    k_packWF<<<dim3(32, 32), 32>>>(Wr0h, pW0F + (long)1*65536, 32);
    k_packWF<<<dim3(32, 32), 32>>>(Wc0h, pW0F + (long)2*65536, 32);
    k_packWF<<<dim3(32, 64), 32>>>(Wu1,  pW1F + (long)0*131072, 64);
    k_packWF<<<dim3(32, 64), 32>>>(Wr1,  pW1F + (long)1*131072, 64);
    k_packWF<<<dim3(32, 64), 32>>>(Wc1,  pW1F + (long)2*131072, 64);
    // x-part weight fragment packs
    k_packWF<<<dim3(32, 32), 32>>>(Wu0, pWXF + (long)0*65536, 32);
    k_packWF<<<dim3(32, 32), 32>>>(Wr0, pWXF + (long)1*65536, 32);
    k_packWF<<<dim3(32, 32), 32>>>(Wc0, pWXF + (long)2*65536, 32);
    // emb fragments, then tensor-core prep: XU/XR/XC
    k_packEF<<<dim3(256, 32), 32>>>();
    k_prepF<<<768, 256>>>(bu0, br0, bc0);
    // h0 fragment split
    k_splitH0F<<<dim3(8, 32), 32>>>();

    // fused persistent kernel: SP recurrence + 8 free-running logits warps
    k_reset<<<1, 1>>>();
    k_recurrentP<<<NCTA_R, 384>>>(bu1, br1, bc1, outb, out);

    // final_state (t=31 odd -> g_H0b holds layer0 final)
    k_copy_final<<<(BB*HH + 255)/256, 256>>>(pH0b, pH1 + (long)(TT-1)*BB*HH,
                                             out + (long)BB*TT*VV);
}

// round 17
// speedup vs baseline: 1.0507x; 1.0507x over previous
#include <cuda_runtime.h>
#include <cuda_bf16.h>
#include <cuda_fp16.h>
#include <cstdint>
#include <stdint.h>
#include <math.h>

#define BB 128
#define TT 32
#define EE 512
#define HH 512
#define VV 10000
#define CF 2048
#define VPAD 10112

#define NCTA_R 128

typedef unsigned long long ull;

// ---------------- scratch (device globals; no allocations allowed) ----------
__device__ float g_h0[BB*HH];
__device__ float g_emb[TT*BB*EE];
__device__ float g_XU[TT*BB*HH];
__device__ float g_XR[TT*BB*HH];
__device__ float g_XC[TT*BB*HH];
__device__ float g_H0a[BB*HH];
__device__ float g_H0b[BB*HH];
__device__ float g_H1[TT*BB*HH];
__device__ float g_u0[BB*HH];
__device__ float g_u1[BB*HH];
__device__ unsigned g_bar;
__device__ unsigned g_gen;
// fragment buffers: tile = 32 lanes x 16B, [kt][pl2][lane32] = 64 uint4/tile
__device__ uint4 g_A2F[TT*16384];        // h1 splits per t (bf16, recurrent use)
__device__ uint4 g_A2H[TT*16384];        // h1 splits per t (fp16, logits use)
__device__ uint4 g_B2F[632*2048];        // out_W frags (fp16; hi plane used)
__device__ uint4 g_embF[256*2048];       // emb frags (bf16)
__device__ uint4 g_H0sFa[16384];
__device__ uint4 g_H0sFb[16384];
__device__ uint4 g_h0sF[16384];
__device__ uint4 g_rhs0F[16384];
__device__ uint4 g_rhs1F[16384];
// weight frags: [gate][nt32][kt][pl2][lane32]
__device__ uint4 g_W0F[3*65536];         // h-part layer0 (K=512)
__device__ uint4 g_WXF[3*65536];         // x-part layer0 (K=512)
__device__ uint4 g_W1F[3*131072];        // layer1 (K=1024)

__device__ __forceinline__ float sigmoidf_(float v){ return 1.f/(1.f+__expf(-v)); }

// packed f32x2 helpers (FFMA2 h0 GEMM)
__device__ __forceinline__ void fma2(ull &acc, ull a, ull b){
    asm("fma.rn.f32x2 %0, %1, %2, %0;" : "+l"(acc) : "l"(a), "l"(b));
}
__device__ __forceinline__ ull dup2(float x){
    ull r; asm("mov.b64 %0, {%1, %1};" : "=l"(r) : "f"(x)); return r;
}
__device__ __forceinline__ float2 unp2(ull v){
    float2 f; asm("mov.b64 {%0, %1}, %2;" : "=f"(f.x), "=f"(f.y) : "l"(v)); return f;
}

// ---------------- mma helpers ------------------------------------------------
__device__ __forceinline__ void mmaU(float* d, const uint4 &a, uint32_t b0, uint32_t b1){
    asm volatile("mma.sync.aligned.m16n8k16.row.col.f32.bf16.bf16.f32 "
        "{%0,%1,%2,%3}, {%4,%5,%6,%7}, {%8,%9}, {%0,%1,%2,%3};"
        : "+f"(d[0]), "+f"(d[1]), "+f"(d[2]), "+f"(d[3])
        : "r"(a.x), "r"(a.y), "r"(a.z), "r"(a.w), "r"(b0), "r"(b1));
}
__device__ __forceinline__ void mmaH(float* d, const uint4 &a, uint32_t b0, uint32_t b1){
    asm volatile("mma.sync.aligned.m16n8k16.row.col.f32.f16.f16.f32 "
        "{%0,%1,%2,%3}, {%4,%5,%6,%7}, {%8,%9}, {%0,%1,%2,%3};"
        : "+f"(d[0]), "+f"(d[1]), "+f"(d[2]), "+f"(d[3])
        : "r"(a.x), "r"(a.y), "r"(a.z), "r"(a.w), "r"(b0), "r"(b1));
}

// split/pack helpers (bf16)
__device__ __forceinline__ uint32_t bfpair(float a, float b){
    __nv_bfloat162 t = __floats2bfloat162_rn(a, b);
    return *reinterpret_cast<uint32_t*>(&t);
}
__device__ __forceinline__ float bfres(float a){
    return a - __bfloat162float(__float2bfloat16(a));
}
__device__ __forceinline__ void store_frag(uint4* dst, const float v[2][4]){
    uint4 HI, LO;
    HI.x = bfpair(v[0][0], v[0][1]); HI.y = bfpair(v[0][2], v[0][3]);
    HI.z = bfpair(v[1][0], v[1][1]); HI.w = bfpair(v[1][2], v[1][3]);
    LO.x = bfpair(bfres(v[0][0]), bfres(v[0][1]));
    LO.y = bfpair(bfres(v[0][2]), bfres(v[0][3]));
    LO.z = bfpair(bfres(v[1][0]), bfres(v[1][1]));
    LO.w = bfpair(bfres(v[1][2]), bfres(v[1][3]));
    __stcg(dst, HI);
    __stcg(dst + 32, LO);
}
// split/pack helpers (fp16)
__device__ __forceinline__ uint32_t hpair(float a, float b){
    __half2 t = __floats2half2_rn(a, b);
    return *reinterpret_cast<uint32_t*>(&t);
}
__device__ __forceinline__ float hres(float a){
    return a - __half2float(__float2half_rn(a));
}
__device__ __forceinline__ void store_fragH(uint4* dst, const float v[2][4]){
    uint4 HI, LO;
    HI.x = hpair(v[0][0], v[0][1]); HI.y = hpair(v[0][2], v[0][3]);
    HI.z = hpair(v[1][0], v[1][1]); HI.w = hpair(v[1][2], v[1][3]);
    LO.x = hpair(hres(v[0][0]), hres(v[0][1]));
    LO.y = hpair(hres(v[0][2]), hres(v[0][3]));
    LO.z = hpair(hres(v[1][0]), hres(v[1][1]));
    LO.w = hpair(hres(v[1][2]), hres(v[1][3]));
    __stcg(dst, HI);
    __stcg(dst + 32, LO);
}

// ---------------- embedding gather ------------------------------------------
__global__ void k_gather(const int* __restrict__ tok, const float* __restrict__ emb){
    int row = blockIdx.x;            // t*BB + b
    int t = row >> 7, b = row & 127;
    int v = tok[b*TT + t];
    const float4* src = (const float4*)(emb + (long)v*EE);
    float4* dst = (float4*)(g_emb + (long)row*EE);
    dst[threadIdx.x] = src[threadIdx.x];
}

// ---------------- h0 GEMM (FFMA2, K=2048, tanh) -----------------------------
__global__ void __launch_bounds__(256)
k_gemmH0(const float* __restrict__ A, const float* __restrict__ Bm,
         const float* __restrict__ bias, float* __restrict__ C)
{
    __shared__ __align__(16) float As[16*132];
    __shared__ __align__(16) float Bs[16*68];
    int tid = threadIdx.x;
    int ty = tid >> 4, tx = tid & 15;
    int n0 = blockIdx.x * 64;
    int ar = tid >> 1, ac = (tid & 1) * 8;
    int br = tid >> 4, bc = (tid & 15) * 4;

    ull acc[4][4] = {};
    float4 a0, a1, b0;

    a0 = *(const float4*)(A + (long)ar*CF + ac);
    a1 = *(const float4*)(A + (long)ar*CF + ac + 4);
    b0 = *(const float4*)(Bm + (long)br*HH + n0 + bc);
    As[(ac+0)*132+ar]=a0.x; As[(ac+1)*132+ar]=a0.y; As[(ac+2)*132+ar]=a0.z; As[(ac+3)*132+ar]=a0.w;
    As[(ac+4)*132+ar]=a1.x; As[(ac+5)*132+ar]=a1.y; As[(ac+6)*132+ar]=a1.z; As[(ac+7)*132+ar]=a1.w;
    *(float4*)&Bs[br*68+bc] = b0;
    __syncthreads();

    int nch = CF >> 4;
    for (int ch = 1; ch <= nch; ch++){
        if (ch < nch){
            int k0 = ch * 16;
            a0 = *(const float4*)(A + (long)ar*CF + k0 + ac);
            a1 = *(const float4*)(A + (long)ar*CF + k0 + ac + 4);
            b0 = *(const float4*)(Bm + (long)(k0+br)*HH + n0 + bc);
        }
#pragma unroll
        for (int kk = 0; kk < 16; kk++){
            ull av[4];
#pragma unroll
            for (int p = 0; p < 4; p++)
                av[p] = *(const ull*)(As + kk*132 + ty*8 + 2*p);
            float4 bv = *(const float4*)(Bs + kk*68 + tx*4);
            ull bb0 = dup2(bv.x), bb1 = dup2(bv.y), bb2 = dup2(bv.z), bb3 = dup2(bv.w);
#pragma unroll
            for (int p = 0; p < 4; p++){
                fma2(acc[p][0], av[p], bb0);
                fma2(acc[p][1], av[p], bb1);
                fma2(acc[p][2], av[p], bb2);
                fma2(acc[p][3], av[p], bb3);
            }
        }
        if (ch < nch){
            __syncthreads();
            As[(ac+0)*132+ar]=a0.x; As[(ac+1)*132+ar]=a0.y; As[(ac+2)*132+ar]=a0.z; As[(ac+3)*132+ar]=a0.w;
            As[(ac+4)*132+ar]=a1.x; As[(ac+5)*132+ar]=a1.y; As[(ac+6)*132+ar]=a1.z; As[(ac+7)*132+ar]=a1.w;
            *(float4*)&Bs[br*68+bc] = b0;
            __syncthreads();
        }
    }

#pragma unroll
    for (int p = 0; p < 4; p++){
#pragma unroll
        for (int j = 0; j < 4; j++){
            float2 v = unp2(acc[p][j]);
            int n = n0 + tx*4 + j;
            float bz = bias[n];
            int row0 = ty*8 + 2*p;
            C[(long)row0*HH + n]     = tanhf(v.x + bz);
            C[(long)(row0+1)*HH + n] = tanhf(v.y + bz);
        }
    }
}

// ---------------- merged weight-fragment packer (9 packs in one launch) -----
// z 0..2: W0 h-part (KT=32); z 3..5: WX x-part (KT=32); z 6..8: W1 (KT=64)
__global__ void k_packAllW(const float* __restrict__ Wu0, const float* __restrict__ Wr0,
                           const float* __restrict__ Wc0,
                           const float* __restrict__ Wu1, const float* __restrict__ Wr1,
                           const float* __restrict__ Wc1)
{
    int nt = blockIdx.x, kt = blockIdx.y, z = blockIdx.z, l = threadIdx.x;
    const float* W;
    uint4* dst;
    int KT;
    if (z < 3){
        const float* s[3] = { Wu0 + (long)EE*HH, Wr0 + (long)EE*HH, Wc0 + (long)EE*HH };
        W = s[z]; dst = &g_W0F[0] + (long)z*65536; KT = 32;
    } else if (z < 6){
        const float* s[3] = { Wu0, Wr0, Wc0 };
        W = s[z-3]; dst = &g_WXF[0] + (long)(z-3)*65536; KT = 32;
    } else {
        const float* s[3] = { Wu1, Wr1, Wc1 };
        W = s[z-6]; dst = &g_W1F[0] + (long)(z-6)*131072; KT = 64;
    }
    if (kt >= KT) return;
    int n0 = nt*16 + (l >> 2), k0 = kt*16 + (l & 3)*2;
    float v[2][4];
    v[0][0] = W[(long)(k0  )*HH + n0];   v[0][1] = W[(long)(k0+1)*HH + n0];
    v[0][2] = W[(long)(k0+8)*HH + n0];   v[0][3] = W[(long)(k0+9)*HH + n0];
    v[1][0] = W[(long)(k0  )*HH + n0+8]; v[1][1] = W[(long)(k0+1)*HH + n0+8];
    v[1][2] = W[(long)(k0+8)*HH + n0+8]; v[1][3] = W[(long)(k0+9)*HH + n0+8];
    store_frag(dst + (long)((nt*KT + kt)*2)*32 + l, v);
}

// out_W -> fp16 B-fragments
__global__ void k_packBF(const float* __restrict__ W){
    int nt = blockIdx.x, kt = blockIdx.y, l = threadIdx.x;
    int n0 = nt*16 + (l >> 2), k0 = kt*16 + (l & 3)*2;
    float v[2][4];
#pragma unroll
    for (int h = 0; h < 2; h++){
        int n = n0 + h*8;
        if (n < VV){
            v[h][0] = W[(long)(k0  )*VV + n]; v[h][1] = W[(long)(k0+1)*VV + n];
            v[h][2] = W[(long)(k0+8)*VV + n]; v[h][3] = W[(long)(k0+9)*VV + n];
        } else {
            v[h][0] = v[h][1] = v[h][2] = v[h][3] = 0.f;
        }
    }
    store_fragH(&g_B2F[0] + (nt*32 + kt)*64 + l, v);
}

__global__ void k_packEF(){
    int mt = blockIdx.x, kt = blockIdx.y, l = threadIdx.x;
    int m0 = mt*16 + (l >> 2), k0 = kt*16 + (l & 3)*2;
    float v[2][4];
    v[0][0] = g_emb[(long)(m0  )*EE + k0];   v[0][1] = g_emb[(long)(m0  )*EE + k0+1];
    v[0][2] = g_emb[(long)(m0+8)*EE + k0];   v[0][3] = g_emb[(long)(m0+8)*EE + k0+1];
    v[1][0] = g_emb[(long)(m0  )*EE + k0+8]; v[1][1] = g_emb[(long)(m0  )*EE + k0+9];
    v[1][2] = g_emb[(long)(m0+8)*EE + k0+8]; v[1][3] = g_emb[(long)(m0+8)*EE + k0+9];
    store_frag(&g_embF[0] + (mt*32 + kt)*64 + l, v);
}

__global__ void k_splitH0F(){
    int mt = blockIdx.x, kt = blockIdx.y, l = threadIdx.x;
    int m0 = mt*16 + (l >> 2), k0 = kt*16 + (l & 3)*2;
    float v[2][4];
    v[0][0] = g_h0[(m0  )*HH + k0];   v[0][1] = g_h0[(m0  )*HH + k0+1];
    v[0][2] = g_h0[(m0+8)*HH + k0];   v[0][3] = g_h0[(m0+8)*HH + k0+1];
    v[1][0] = g_h0[(m0  )*HH + k0+8]; v[1][1] = g_h0[(m0  )*HH + k0+9];
    v[1][2] = g_h0[(m0+8)*HH + k0+8]; v[1][3] = g_h0[(m0+8)*HH + k0+9];
    int off = (mt*32 + kt)*64 + l;
    store_frag(&g_H0sFb[0] + off, v);
    store_frag(&g_h0sF[0] + off, v);
}

// ---------------- prep GEMM via fragments: XU/XR/XC = emb@Wx + b ------------
__global__ void __launch_bounds__(256)
k_prepF(const float* __restrict__ bu0, const float* __restrict__ br0,
        const float* __restrict__ bc0)
{
    int lane = threadIdx.x & 31, w = threadIdx.x >> 5;
    int gwp = blockIdx.x * 8 + w;
    int gate = gwp >> 11;
    int rem = gwp & 2047;
    int mg = rem >> 4, ng = rem & 15;

    const float* bias = (gate == 0) ? bu0 : (gate == 1) ? br0 : bc0;
    float* C = (gate == 0) ? g_XU : (gate == 1) ? g_XR : g_XC;

    const uint4* A0 = &g_embF[0] + (long)(mg*2+0)*2048 + lane;
    const uint4* A1 = &g_embF[0] + (long)(mg*2+1)*2048 + lane;
    const uint4* B0 = &g_WXF[0] + (long)gate*65536 + (long)(ng*2+0)*2048 + lane;
    const uint4* B1 = &g_WXF[0] + (long)gate*65536 + (long)(ng*2+1)*2048 + lane;

    float acc[2][2][2][4];
#pragma unroll
    for (int i = 0; i < 2; i++)
#pragma unroll
        for (int j = 0; j < 2; j++)
#pragma unroll
            for (int g = 0; g < 2; g++)
#pragma unroll
                for (int q = 0; q < 4; q++) acc[i][j][g][q] = 0.f;

    uint4 a0h = A0[0], a0l = A0[32], a1h = A1[0], a1l = A1[32];
    uint4 b0h = B0[0], b0l = B0[32], b1h = B1[0], b1l = B1[32];
#pragma unroll 4
    for (int kt = 0; kt < 32; kt++){
        uint4 na0h, na0l, na1h, na1l, nb0h, nb0l, nb1h, nb1l;
        if (kt + 1 < 32){
            int o = (kt+1)*64;
            na0h = A0[o]; na0l = A0[o+32]; na1h = A1[o]; na1l = A1[o+32];
            nb0h = B0[o]; nb0l = B0[o+32]; nb1h = B1[o]; nb1l = B1[o+32];
        } else {
            na0h=a0h; na0l=a0l; na1h=a1h; na1l=a1l;
            nb0h=b0h; nb0l=b0l; nb1h=b1h; nb1l=b1l;
        }
        mmaU(acc[0][0][0], a0h, b0h.x, b0h.y); mmaU(acc[0][0][1], a0h, b0h.z, b0h.w);
        mmaU(acc[0][0][0], a0l, b0h.x, b0h.y); mmaU(acc[0][0][1], a0l, b0h.z, b0h.w);
        mmaU(acc[0][0][0], a0h, b0l.x, b0l.y); mmaU(acc[0][0][1], a0h, b0l.z, b0l.w);

        mmaU(acc[0][1][0], a0h, b1h.x, b1h.y); mmaU(acc[0][1][1], a0h, b1h.z, b1h.w);
        mmaU(acc[0][1][0], a0l, b1h.x, b1h.y); mmaU(acc[0][1][1], a0l, b1h.z, b1h.w);
        mmaU(acc[0][1][0], a0h, b1l.x, b1l.y); mmaU(acc[0][1][1], a0h, b1l.z, b1l.w);

        mmaU(acc[1][0][0], a1h, b0h.x, b0h.y); mmaU(acc[1][0][1], a1h, b0h.z, b0h.w);
        mmaU(acc[1][0][0], a1l, b0h.x, b0h.y); mmaU(acc[1][0][1], a1l, b0h.z, b0h.w);
        mmaU(acc[1][0][0], a1h, b0l.x, b0l.y); mmaU(acc[1][0][1], a1h, b0l.z, b0l.w);

        mmaU(acc[1][1][0], a1h, b1h.x, b1h.y); mmaU(acc[1][1][1], a1h, b1h.z, b1h.w);
        mmaU(acc[1][1][0], a1l, b1h.x, b1h.y); mmaU(acc[1][1][1], a1l, b1h.z, b1h.w);
        mmaU(acc[1][1][0], a1h, b1l.x, b1l.y); mmaU(acc[1][1][1], a1h, b1l.z, b1l.w);

        a0h=na0h; a0l=na0l; a1h=na1h; a1l=na1l;
        b0h=nb0h; b0l=nb0l; b1h=nb1h; b1l=nb1l;
    }

    int lr = lane >> 2, lc2 = (lane & 3) * 2;
#pragma unroll
    for (int i = 0; i < 2; i++){
        int m = mg*32 + i*16 + lr;
        long base = (long)m*HH;
#pragma unroll
        for (int j = 0; j < 2; j++){
#pragma unroll
            for (int g = 0; g < 2; g++){
                int n = ng*32 + j*16 + g*8 + lc2;
                const float* a4 = acc[i][j][g];
                float bz0 = bias[n], bz1 = bias[n+1];
                C[base + n]            = a4[0] + bz0;
                C[base + n + 1]        = a4[1] + bz1;
                C[base + 8*HH + n]     = a4[2] + bz0;
                C[base + 8*HH + n + 1] = a4[3] + bz1;
            }
        }
    }
}

// ---------------- barrier reset + SP-only grid barrier ----------------------
__global__ void k_reset(){ g_bar = 0u; g_gen = 0u; }

__device__ __forceinline__ void gsyncSP(unsigned &my_gen){
    asm volatile("bar.sync 1, 128;" ::: "memory");
    if (threadIdx.x == 0){
        __threadfence();
        my_gen++;
        if (atomicAdd(&g_bar, 1u) == NCTA_R-1u){
            atomicExch(&g_bar, 0u);
            __threadfence();
            atomicExch(&g_gen, my_gen);
        } else {
            while (*(volatile unsigned*)&g_gen < my_gen) { }
            __threadfence();
        }
    }
    asm volatile("bar.sync 1, 128;" ::: "memory");
}

// ---------------- single-stream fragment GEMM (prefetch-1) ------------------
template<int KT>
__device__ __forceinline__ void frag_mm(const uint4* __restrict__ A0,
                                        const uint4* __restrict__ A1,
                                        const uint4* __restrict__ Wb,
                                        float acc[2][4])
{
#pragma unroll
    for (int g = 0; g < 2; g++)
#pragma unroll
        for (int q = 0; q < 4; q++) acc[g][q] = 0.f;

    uint4 cAh = __ldcg(A0), cAl = __ldcg(A0 + 32);
    uint4 cWh = Wb[0], cWl = Wb[32];
#pragma unroll 4
    for (int kt = 0; kt < KT; kt++){
        uint4 nAh, nAl, nWh, nWl;
        if (kt + 1 < KT){
            const uint4* an = ((kt+1) < 32) ? (A0 + (kt+1)*64) : (A1 + (kt+1-32)*64);
            nAh = __ldcg(an); nAl = __ldcg(an + 32);
            nWh = Wb[(kt+1)*64]; nWl = Wb[(kt+1)*64 + 32];
        } else { nAh = cAh; nAl = cAl; nWh = cWh; nWl = cWl; }
        mmaU(acc[0], cAh, cWh.x, cWh.y); mmaU(acc[1], cAh, cWh.z, cWh.w);
        mmaU(acc[0], cAl, cWh.x, cWh.y); mmaU(acc[1], cAl, cWh.z, cWh.w);
        mmaU(acc[0], cAh, cWl.x, cWl.y); mmaU(acc[1], cAh, cWl.z, cWl.w);
        cAh = nAh; cAl = nAl; cWh = nWh; cWl = nWl;
    }
}

// ---------------- logits warp-tile: fp16 2-term, 32x32 for timestep t -------
// A2H read with plain LDG (L1-cached): safe — first touch of these addresses
// happens only after the publish-poll, and L1 is flushed per launch.
__device__ __forceinline__ void logits_tile(int t, int mg, int ng, int lane,
                                            const float* __restrict__ bias,
                                            float* __restrict__ out)
{
    const uint4* A0 = &g_A2H[0] + (long)t*16384 + (mg*2+0)*2048 + lane;
    const uint4* A1 = &g_A2H[0] + (long)t*16384 + (mg*2+1)*2048 + lane;
    const uint4* B0 = &g_B2F[0] + (long)(ng*2+0)*2048 + lane;
    const uint4* B1 = &g_B2F[0] + (long)(ng*2+1)*2048 + lane;

    float acc[2][2][2][4];
#pragma unroll
    for (int i = 0; i < 2; i++)
#pragma unroll
        for (int j = 0; j < 2; j++)
#pragma unroll
            for (int g = 0; g < 2; g++)
#pragma unroll
                for (int q = 0; q < 4; q++) acc[i][j][g][q] = 0.f;

    uint4 a0h = A0[0], a0l = A0[32], a1h = A1[0], a1l = A1[32];
    uint4 b0h = B0[0], b1h = B1[0];
#pragma unroll 4
    for (int kt = 0; kt < 32; kt++){
        uint4 na0h, na0l, na1h, na1l, nb0h, nb1h;
        if (kt + 1 < 32){
            int o = (kt+1)*64;
            na0h = A0[o]; na0l = A0[o+32];
            na1h = A1[o]; na1l = A1[o+32];
            nb0h = B0[o]; nb1h = B1[o];
        } else {
            na0h=a0h; na0l=a0l; na1h=a1h; na1l=a1l;
            nb0h=b0h; nb1h=b1h;
        }
        mmaH(acc[0][0][0], a0h, b0h.x, b0h.y); mmaH(acc[0][0][1], a0h, b0h.z, b0h.w);
        mmaH(acc[0][0][0], a0l, b0h.x, b0h.y); mmaH(acc[0][0][1], a0l, b0h.z, b0h.w);

        mmaH(acc[0][1][0], a0h, b1h.x, b1h.y); mmaH(acc[0][1][1], a0h, b1h.z, b1h.w);
        mmaH(acc[0][1][0], a0l, b1h.x, b1h.y); mmaH(acc[0][1][1], a0l, b1h.z, b1h.w);

        mmaH(acc[1][0][0], a1h, b0h.x, b0h.y); mmaH(acc[1][0][1], a1h, b0h.z, b0h.w);
        mmaH(acc[1][0][0], a1l, b0h.x, b0h.y); mmaH(acc[1][0][1], a1l, b0h.z, b0h.w);

        mmaH(acc[1][1][0], a1h, b1h.x, b1h.y); mmaH(acc[1][1][1], a1h, b1h.z, b1h.w);
        mmaH(acc[1][1][0], a1l, b1h.x, b1h.y); mmaH(acc[1][1][1], a1l, b1h.z, b1h.w);

        a0h=na0h; a0l=na0l; a1h=na1h; a1l=na1l;
        b0h=nb0h; b1h=nb1h;
    }

    int lr = lane >> 2, lc2 = (lane & 3) * 2;
    long sB = TT * (long)VV;
#pragma unroll
    for (int i = 0; i < 2; i++){
        int b = mg*32 + i*16 + lr;
        long base = (long)b*sB + (long)t*VV;
#pragma unroll
        for (int j = 0; j < 2; j++){
#pragma unroll
            for (int g = 0; g < 2; g++){
                int n = (ng*2 + j)*16 + g*8 + lc2;
                const float* a4 = acc[i][j][g];
                if (n < VV){
                    float bz = bias[n];
                    out[base + n]        = a4[0] + bz;
                    out[base + 8*sB + n] = a4[2] + bz;
                }
                if (n + 1 < VV){
                    float bz = bias[n+1];
                    out[base + n + 1]        = a4[1] + bz;
                    out[base + 8*sB + n + 1] = a4[3] + bz;
                }
            }
        }
    }
}

// ---------------- fused persistent kernel: SP warps + free-running logits ---
__global__ void __launch_bounds__(256, 1)
k_recurrentP(const float* __restrict__ bu1, const float* __restrict__ br1,
             const float* __restrict__ bc1,
             const float* __restrict__ outb, float* __restrict__ out)
{
    int tid = threadIdx.x, w = tid >> 5, lane = tid & 31;
    int lr = lane >> 2, lc2 = (lane & 3) * 2;

    if (w >= 4){
        // ---- free-running logits warps: 512 grid-wide, poll g_gen ----
        int lw = blockIdx.x * 4 + (w - 4);
        for (long idx = lw; idx < (long)TT*1264; idx += 512){
            int t = (int)(idx / 1264);
            int j = (int)(idx % 1264);
            unsigned need = 2u*t + 4u;
            while (*(volatile unsigned*)&g_gen < need) __nanosleep(200);
            __threadfence();
            logits_tile(t, j & 3, j >> 2, lane, outb, out);
        }
        return;
    }

    // ---- SP warps (0-3): layer-pipelined recurrence ----
    int gw = blockIdx.x * 4 + w;            // 0..511
    unsigned my_gen = 0;

    int gate = gw >> 8;
    int ntA  = (gw >> 3) & 31;
    int mtA  = gw & 7;
    int sel = gw & 1;
    int u2  = gw >> 1;
    int ntB = (u2 >> 3) & 31;
    int mtB = u2 & 7;

    const uint4* WA0 = &g_W0F[0] + (long)gate*65536 + ntA*2048 + lane;
    const uint4* WA1 = &g_W1F[0] + (long)gate*131072 + ntA*4096 + lane;
    const uint4* WB0 = &g_W0F[0] + (long)2*65536   + ntB*2048 + lane;
    const uint4* WB1 = &g_W1F[0] + (long)2*131072  + ntB*4096 + lane;

    uint4* bufF[2] = { &g_H0sFa[0], &g_H0sFb[0] };

    for (int i = 0; i <= TT; i++){
        bool doL0 = (i < TT), doL1 = (i >= 1);
        int t0 = i, t1 = i - 1;
        const uint4* H0rdF = bufF[(t0 + 1) & 1];
        uint4*       H0wrF = bufF[t0 & 1];
        const float* h0prev = (t0 == 0) ? g_h0 : ((t0 & 1) ? g_H0a : g_H0b);
        float*       h0cur  = (t0 & 1) ? g_H0b : g_H0a;
        const float* h1prev = (t1 == 0) ? g_h0 : g_H1 + (long)(t1-1)*BB*HH;
        float*       h1cur  = g_H1 + (long)t1*BB*HH;
        const float* XU = g_XU + (long)t0*BB*HH;
        const float* XR = g_XR + (long)t0*BB*HH;
        const float* XC = g_XC + (long)t0*BB*HH;
        const uint4* h1sF = (t1 == 0) ? &g_h0sF[0] : &g_A2F[0] + (long)(t1-1)*16384;

        // ===== SP1: L0 gates(t0) || L1 gates(t1), shared A first half =====
        {
            float acc0[2][4], acc1[2][4];
#pragma unroll
            for (int g = 0; g < 2; g++)
#pragma unroll
                for (int q = 0; q < 4; q++){ acc0[g][q] = 0.f; acc1[g][q] = 0.f; }

            const uint4* Ab  = H0rdF + mtA*2048 + lane;
            const uint4* A1b = h1sF + mtA*2048 + lane;
            int KTs = doL1 ? 64 : 32;

            uint4 cA0 = __ldcg(Ab), cA1 = __ldcg(Ab + 32);
            uint4 cW00 = WA0[0], cW01 = WA0[32];
            uint4 cW10, cW11;
            if (doL1){ cW10 = WA1[0]; cW11 = WA1[32]; }

#pragma unroll 4
            for (int kt = 0; kt < 64; kt++){
                if (kt >= KTs) break;
                uint4 nA0, nA1, nW00, nW01, nW10, nW11;
                int nk = kt + 1;
                bool hn = nk < KTs;
                if (hn){
                    const uint4* an = (nk < 32) ? (Ab + nk*64) : (A1b + (nk-32)*64);
                    nA0 = __ldcg(an); nA1 = __ldcg(an + 32);
                    if (nk < 32){ nW00 = WA0[nk*64]; nW01 = WA0[nk*64 + 32]; }
                    if (doL1){ nW10 = WA1[nk*64]; nW11 = WA1[nk*64 + 32]; }
                }
                if (doL0 && kt < 32){
                    mmaU(acc0[0], cA0, cW00.x, cW00.y); mmaU(acc0[1], cA0, cW00.z, cW00.w);
                    mmaU(acc0[0], cA1, cW00.x, cW00.y); mmaU(acc0[1], cA1, cW00.z, cW00.w);
                    mmaU(acc0[0], cA0, cW01.x, cW01.y); mmaU(acc0[1], cA0, cW01.z, cW01.w);
                }
                if (doL1){
                    mmaU(acc1[0], cA0, cW10.x, cW10.y); mmaU(acc1[1], cA0, cW10.z, cW10.w);
                    mmaU(acc1[0], cA1, cW10.x, cW10.y); mmaU(acc1[1], cA1, cW10.z, cW10.w);
                    mmaU(acc1[0], cA0, cW11.x, cW11.y); mmaU(acc1[1], cA0, cW11.z, cW11.w);
                }
                if (hn){
                    cA0 = nA0; cA1 = nA1;
                    if (nk < 32){ cW00 = nW00; cW01 = nW01; }
                    if (doL1){ cW10 = nW10; cW11 = nW11; }
                }
            }

            int r0 = mtA*16 + lr;
            if (doL0){
                if (gate == 0){
#pragma unroll
                    for (int g = 0; g < 2; g++){
                        int cg = ntA*16 + g*8 + lc2;
                        int i0 = r0*HH + cg, i1 = (r0+8)*HH + cg;
                        __stcg(&g_u0[i0],   sigmoidf_(acc0[g][0] + XU[i0]));
                        __stcg(&g_u0[i0+1], sigmoidf_(acc0[g][1] + XU[i0+1]));
                        __stcg(&g_u0[i1],   sigmoidf_(acc0[g][2] + XU[i1]));
                        __stcg(&g_u0[i1+1], sigmoidf_(acc0[g][3] + XU[i1+1]));
                    }
                } else {
                    float vv[2][4];
#pragma unroll
                    for (int g = 0; g < 2; g++){
                        int cg = ntA*16 + g*8 + lc2;
                        int i0 = r0*HH + cg, i1 = (r0+8)*HH + cg;
                        vv[g][0] = sigmoidf_(acc0[g][0] + XR[i0])   * __ldcg(&h0prev[i0]);
                        vv[g][1] = sigmoidf_(acc0[g][1] + XR[i0+1]) * __ldcg(&h0prev[i0+1]);
                        vv[g][2] = sigmoidf_(acc0[g][2] + XR[i1])   * __ldcg(&h0prev[i1]);
                        vv[g][3] = sigmoidf_(acc0[g][3] + XR[i1+1]) * __ldcg(&h0prev[i1+1]);
                    }
                    store_frag(&g_rhs0F[0] + mtA*2048 + ntA*64 + lane, vv);
                }
            }
            if (doL1){
                if (gate == 0){
#pragma unroll
                    for (int g = 0; g < 2; g++){
                        int cg = ntA*16 + g*8 + lc2;
                        int i0 = r0*HH + cg, i1 = (r0+8)*HH + cg;
                        __stcg(&g_u1[i0],   sigmoidf_(acc1[g][0] + bu1[cg]));
                        __stcg(&g_u1[i0+1], sigmoidf_(acc1[g][1] + bu1[cg+1]));
                        __stcg(&g_u1[i1],   sigmoidf_(acc1[g][2] + bu1[cg]));
                        __stcg(&g_u1[i1+1], sigmoidf_(acc1[g][3] + bu1[cg+1]));
                    }
                } else {
                    float vv[2][4];
#pragma unroll
                    for (int g = 0; g < 2; g++){
                        int cg = ntA*16 + g*8 + lc2;
                        int i0 = r0*HH + cg, i1 = (r0+8)*HH + cg;
                        vv[g][0] = sigmoidf_(acc1[g][0] + br1[cg])   * __ldcg(&h1prev[i0]);
                        vv[g][1] = sigmoidf_(acc1[g][1] + br1[cg+1]) * __ldcg(&h1prev[i0+1]);
                        vv[g][2] = sigmoidf_(acc1[g][2] + br1[cg])   * __ldcg(&h1prev[i1]);
                        vv[g][3] = sigmoidf_(acc1[g][3] + br1[cg+1]) * __ldcg(&h1prev[i1+1]);
                    }
                    store_frag(&g_rhs1F[0] + mtA*2048 + ntA*64 + lane, vv);
                }
            }
        }
        gsyncSP(my_gen);

        // ===== SP2: L0 c(t0) on even warps || L1 c(t1) on odd warps =====
        if (sel == 0){
            if (doL0){
                float acc[2][4];
                const uint4* A0 = &g_rhs0F[0] + mtB*2048 + lane;
                frag_mm<32>(A0, A0, WB0, acc);
                int r0 = mtB*16 + lr;
                float vv[2][4];
#pragma unroll
                for (int g = 0; g < 2; g++){
                    int cg = ntB*16 + g*8 + lc2;
                    int idx[4] = { r0*HH + cg, r0*HH + cg + 1,
                                   (r0+8)*HH + cg, (r0+8)*HH + cg + 1 };
#pragma unroll
                    for (int j = 0; j < 4; j++){
                        float c0 = tanhf(acc[g][j] + XC[idx[j]]);
                        float uu = __ldcg(&g_u0[idx[j]]);
                        float hp = __ldcg(&h0prev[idx[j]]);
                        float hn = uu*hp + (1.f - uu)*c0;
                        __stcg(&h0cur[idx[j]], hn);
                        vv[g][j] = hn;
                    }
                }
                store_frag(H0wrF + mtB*2048 + ntB*64 + lane, vv);
            }
        } else {
            if (doL1){
                float acc[2][4];
                const uint4* A0 = bufF[t1 & 1] + mtB*2048 + lane;
                const uint4* A1 = &g_rhs1F[0] + mtB*2048 + lane;
                frag_mm<64>(A0, A1, WB1, acc);
                int r0 = mtB*16 + lr;
                float vv[2][4];
#pragma unroll
                for (int g = 0; g < 2; g++){
                    int cg = ntB*16 + g*8 + lc2;
#pragma unroll
                    for (int j = 0; j < 4; j++){
                        int row = r0 + ((j >> 1) ? 8 : 0);
                        int col = cg + (j & 1);
                        int idx = row*HH + col;
                        float c1 = tanhf(acc[g][j] + bc1[col]);
                        float uu = __ldcg(&g_u1[idx]);
                        float hp = __ldcg(&h1prev[idx]);
                        float hn = uu*hp + (1.f - uu)*c1;
                        __stcg(&h1cur[idx], hn);
                        vv[g][j] = hn;
                    }
                }
                store_frag(&g_A2F[0] + (long)t1*16384 + mtB*2048 + ntB*64 + lane, vv);
                store_fragH(&g_A2H[0] + (long)t1*16384 + mtB*2048 + ntB*64 + lane, vv);
            }
        }
        gsyncSP(my_gen);
    }
}

// ---------------- final state copy ------------------------------------------
__global__ void k_copy_final(const float* __restrict__ h0f,
                             const float* __restrict__ h1f,
                             float* __restrict__ out)
{
    int i = blockIdx.x * blockDim.x + threadIdx.x;
    if (i < BB*HH){
        out[i]         = h0f[i];
        out[BB*HH + i] = h1f[i];
    }
}

// ---------------- launch ----------------------------------------------------
extern "C" void kernel_launch(void* const* d_in, const int* in_sizes, int n_in,
                              void* d_out, int out_size)
{
    const float* cnn = (const float*)d_in[0];
    const int*   tok = (const int*)  d_in[1];
    const float* emb = (const float*)d_in[2];
    const float* inW = (const float*)d_in[3];
    const float* inb = (const float*)d_in[4];
    const float* Wu0 = (const float*)d_in[5];
    const float* bu0 = (const float*)d_in[6];
    const float* Wr0 = (const float*)d_in[7];
    const float* br0 = (const float*)d_in[8];
    const float* Wc0 = (const float*)d_in[9];
    const float* bc0 = (const float*)d_in[10];
    const float* Wu1 = (const float*)d_in[11];
    const float* bu1 = (const float*)d_in[12];
    const float* Wr1 = (const float*)d_in[13];
    const float* br1 = (const float*)d_in[14];
    const float* Wc1 = (const float*)d_in[15];
    const float* bc1 = (const float*)d_in[16];
    const float* outW= (const float*)d_in[17];
    const float* outb= (const float*)d_in[18];
    float* out = (float*)d_out;

    float *ph0,*pH0b,*pH1;
    cudaGetSymbolAddress((void**)&ph0,  g_h0);
    cudaGetSymbolAddress((void**)&pH0b, g_H0b);
    cudaGetSymbolAddress((void**)&pH1,  g_H1);

    // h0 = tanh(cnn @ in_W + in_b)
    k_gemmH0<<<8, 256>>>(cnn, inW, inb, ph0);
    // gather embeddings
    k_gather<<<TT*BB, 128>>>(tok, emb);
    // logits-weight fragment pack (fp16)
    k_packBF<<<dim3(632, 32), 32>>>(outW);
    // ALL recurrent/x-part weight fragment packs in one launch
    k_packAllW<<<dim3(32, 64, 9), 32>>>(Wu0, Wr0, Wc0, Wu1, Wr1, Wc1);
    // emb fragments, then tensor-core prep: XU/XR/XC
    k_packEF<<<dim3(256, 32), 32>>>();
    k_prepF<<<768, 256>>>(bu0, br0, bc0);
    // h0 fragment split
    k_splitH0F<<<dim3(8, 32), 32>>>();

    // fused persistent kernel: SP recurrence + 4 free-running logits warps
    k_reset<<<1, 1>>>();
    k_recurrentP<<<NCTA_R, 256>>>(bu1, br1, bc1, outb, out);

    // final_state (t=31 odd -> g_H0b holds layer0 final)
    k_copy_final<<<(BB*HH + 255)/256, 256>>>(pH0b, pH1 + (long)(TT-1)*BB*HH,
                                             out + (long)BB*TT*VV);
}